// round 17
// baseline (speedup 1.0000x reference)
#include <cuda_runtime.h>
#include <math.h>

#define MAX_N    16
#define NBINS    4096
#define SUBB     4096
#define CAND_MAX 16384
#define SK_MAX   8192
#define HT       1024
#define BPB      18

__device__ unsigned int       g_sub[MAX_N * SUBB];   // relative-digit histogram
__device__ int                g_count[MAX_N];
__device__ unsigned int       g_T24[MAX_N];
__device__ unsigned long long g_cand[MAX_N * CAND_MAX];
__device__ unsigned long long g_trim[MAX_N * CAND_MAX];  // overflow scatter space

__device__ __forceinline__ unsigned int mono_f32(float f) {
    unsigned int u = __float_as_uint(f);
    return (u & 0x80000000u) ? ~u : (u | 0x80000000u);
}
__device__ __forceinline__ float inv_mono(unsigned int m) {
    unsigned int u = (m & 0x80000000u) ? (m & 0x7FFFFFFFu) : ~m;
    return __uint_as_float(u);
}

// Suffix-scan threshold over a 4096-bin hist in sh[]. blockDim = 1024; thread
// t owns bins [4t,4t+4). Largest bin with suffix >= st -> *out; suffix above
// it -> *outAbove. Single writer. 2 barriers.
__device__ __forceinline__ void suffix_threshold(const unsigned int* sh,
                                                 unsigned int st,
                                                 unsigned int* warp_tot,
                                                 int* out, unsigned int* outAbove) {
    const int t = threadIdx.x, lane = t & 31, wid = t >> 5;
    unsigned int h0 = sh[t * 4], h1 = sh[t * 4 + 1], h2 = sh[t * 4 + 2], h3 = sh[t * 4 + 3];
    unsigned int seg = h0 + h1 + h2 + h3;
    unsigned int suf = seg;
#pragma unroll
    for (int d = 1; d < 32; d <<= 1) {
        unsigned int v = __shfl_down_sync(0xFFFFFFFFu, suf, d);
        if (lane + d < 32) suf += v;
    }
    if (lane == 0) warp_tot[wid] = suf;
    __syncthreads();
    if (wid == 0) {
        unsigned int wv = warp_tot[lane];
        unsigned int wsuf = wv;
#pragma unroll
        for (int d = 1; d < 32; d <<= 1) {
            unsigned int v = __shfl_down_sync(0xFFFFFFFFu, wsuf, d);
            if (lane + d < 32) wsuf += v;
        }
        warp_tot[lane] = wsuf - wv;
    }
    __syncthreads();
    unsigned int S  = suf + warp_tot[wid];
    unsigned int sN = S - seg;
    unsigned int s3 = sN + h3;
    unsigned int s2 = s3 + h2;
    unsigned int s1 = s2 + h1;
    unsigned int s0 = S;
    if      (s3 >= st && sN < st) { *out = t * 4 + 3; *outAbove = sN; }
    else if (s2 >= st && s3 < st) { *out = t * 4 + 2; *outAbove = s3; }
    else if (s1 >= st && s2 < st) { *out = t * 4 + 1; *outAbove = s2; }
    else if (s0 >= st && s1 < st) { *out = t * 4 + 0; *outAbove = s1; }
}

// ---------------------------------------------------------------------------
// K1: 24-bit sampled threshold (1 block/batch). 16384 strided samples.
// ---------------------------------------------------------------------------
__global__ void __launch_bounds__(1024) sample_thresh_kernel(
        const float* __restrict__ scores, int A, int k) {
    __shared__ unsigned int sh[NBINS];
    __shared__ unsigned int warp_tot[32];
    __shared__ int sT1, sT2;
    __shared__ unsigned int sS1, sDummy;
    const int b = blockIdx.x;
    const int t = threadIdx.x;

    for (int i = t; i < NBINS; i += 1024) sh[i] = 0;
    if (t == 0) g_count[b] = 0;
    __syncthreads();

    const size_t base = (size_t)b * (size_t)A;
    const int A4 = A >> 2;

    if ((A & 3) == 0 && A4 >= 4096) {
        const float4* s4 = (const float4*)(scores + base);
        unsigned int m[16];
#pragma unroll
        for (int r = 0; r < 4; r++) {
            int j = t + r * 1024;
            size_t pos = ((size_t)j * (size_t)A4) >> 12;
            float4 v = s4[pos];
            m[r * 4 + 0] = mono_f32(v.x);
            m[r * 4 + 1] = mono_f32(v.y);
            m[r * 4 + 2] = mono_f32(v.z);
            m[r * 4 + 3] = mono_f32(v.w);
        }
#pragma unroll
        for (int q = 0; q < 16; q++) atomicAdd(&sh[m[q] >> 20], 1u);
        __syncthreads();

        long long tgt = (16384LL * 7LL * (long long)k) / (4LL * (long long)A);  // ~3.5k
        if (tgt < 1) tgt = 1;
        if (tgt > 16384) tgt = 16384;
        const unsigned int st = (unsigned)tgt;

        suffix_threshold(sh, st, warp_tot, &sT1, &sS1);
        __syncthreads();
        const int T1 = sT1;
        const unsigned int S1 = sS1;
        __syncthreads();

        for (int i = t; i < NBINS; i += 1024) sh[i] = 0;
        __syncthreads();
#pragma unroll
        for (int q = 0; q < 16; q++)
            if ((int)(m[q] >> 20) == T1) atomicAdd(&sh[(m[q] >> 8) & 0xFFFu], 1u);
        __syncthreads();

        suffix_threshold(sh, st - S1, warp_tot, &sT2, &sDummy);
        __syncthreads();
        if (t == 0) g_T24[b] = ((unsigned)T1 << 12) | (unsigned)sT2;
    } else {
        for (int i = t; i < A; i += 1024)
            atomicAdd(&sh[mono_f32(scores[base + i]) >> 20], 1u);
        __syncthreads();
        suffix_threshold(sh, (unsigned)min(k, A), warp_tot, &sT1, &sS1);
        __syncthreads();
        if (t == 0) g_T24[b] = (unsigned)sT1 << 12;
    }
}

// ---------------------------------------------------------------------------
__device__ __forceinline__ void push_warp(int b, unsigned int T24,
                                          bool pred, unsigned long long key) {
    unsigned int bal = __ballot_sync(0xFFFFFFFFu, pred);
    if (!bal) return;
    const int lane = threadIdx.x & 31;
    const int leader = __ffs(bal) - 1;
    int base = 0;
    if (lane == leader) base = atomicAdd(&g_count[b], __popc(bal));
    base = __shfl_sync(0xFFFFFFFFu, base, leader);
    if (pred) {
        int pos = base + __popc(bal & ((1u << lane) - 1u));
        if (pos < CAND_MAX) g_cand[b * CAND_MAX + pos] = key;
        unsigned int dig = min((unsigned)(key >> 40) - T24, 4095u);
        atomicAdd(&g_sub[b * SUBB + dig], 1u);
    }
}

// ---------------------------------------------------------------------------
// K2: single full sweep — compact (m>>8) >= T24 + relative-digit histogram.
// grid (BPB, N) x HT
// ---------------------------------------------------------------------------
__global__ void __launch_bounds__(HT) compact_kernel(
        const float* __restrict__ scores, int A) {
    const int b = blockIdx.y;
    const unsigned int T24 = g_T24[b];
    const size_t base = (size_t)b * (size_t)A;
    const int lane = threadIdx.x & 31;

    if ((A & 3) == 0) {
        const float4* s4 = (const float4*)(scores + base);
        const int A4 = A >> 2;
        const int warp0 = blockIdx.x * (HT / 32) + (threadIdx.x >> 5);
        for (int i0 = warp0 * 32; i0 < A4; i0 += BPB * HT) {
            const int i = i0 + lane;
            const bool in = i < A4;
            float4 v;
            if (in) v = s4[i];
            unsigned int o = (unsigned)(i << 2);
            unsigned int mx = in ? mono_f32(v.x) : 0u;
            unsigned int my = in ? mono_f32(v.y) : 0u;
            unsigned int mz = in ? mono_f32(v.z) : 0u;
            unsigned int mw = in ? mono_f32(v.w) : 0u;
            push_warp(b, T24, in && (mx >> 8) >= T24,
                      ((unsigned long long)mx << 32) | (0xFFFFFFFFu - (o + 0u)));
            push_warp(b, T24, in && (my >> 8) >= T24,
                      ((unsigned long long)my << 32) | (0xFFFFFFFFu - (o + 1u)));
            push_warp(b, T24, in && (mz >> 8) >= T24,
                      ((unsigned long long)mz << 32) | (0xFFFFFFFFu - (o + 2u)));
            push_warp(b, T24, in && (mw >> 8) >= T24,
                      ((unsigned long long)mw << 32) | (0xFFFFFFFFu - (o + 3u)));
        }
    } else {
        const int warp0 = blockIdx.x * (HT / 32) + (threadIdx.x >> 5);
        for (int i0 = warp0 * 32; i0 < A; i0 += BPB * HT) {
            const int i = i0 + lane;
            const bool in = i < A;
            unsigned int m = in ? mono_f32(scores[base + i]) : 0u;
            push_warp(b, T24, in && (m >> 8) >= T24,
                      ((unsigned long long)m << 32) | (0xFFFFFFFFu - (unsigned)i));
        }
    }
}

// ---------------------------------------------------------------------------
__device__ __forceinline__ void decode_one(unsigned long long key, int r,
                                           const float* __restrict__ anchors,
                                           const float* __restrict__ breg,
                                           float* __restrict__ out,
                                           size_t base, int b, int k) {
    const float CLIP = 4.135166556742356f;   // log(1000/16)
    unsigned int idx = 0xFFFFFFFFu - (unsigned int)(key & 0xFFFFFFFFull);
    float sc = inv_mono((unsigned int)(key >> 32));
    size_t g4 = (base + (size_t)idx) * 4;

    float4 box = *(const float4*)(anchors + g4);
    float4 rc  = *(const float4*)(breg + g4);

    float w  = box.z - box.x + 1.0f;
    float h  = box.w - box.y + 1.0f;
    float cx = box.x + 0.5f * w;
    float cy = box.y + 0.5f * h;

    float dw = fminf(rc.z, CLIP);
    float dh = fminf(rc.w, CLIP);

    float pcx = rc.x * w + cx;
    float pcy = rc.y * h + cy;
    float pw  = expf(dw) * w;
    float ph  = expf(dh) * h;

    float* o = out + ((size_t)b * k + r) * 5;
    o[0] = pcx - 0.5f * pw;
    o[1] = pcy - 0.5f * ph;
    o[2] = pcx + 0.5f * pw - 1.0f;
    o[3] = pcy + 0.5f * ph - 1.0f;
    o[4] = sc;
}

// ---------------------------------------------------------------------------
// K3: one block per batch. Guarded exact fallback (rare) + counting-sort rank
// + decode. start[d] = #candidates with digit > d; scatter by digit cursor;
// rank = start[digit] + tiny intra-group compare scan. grid N x 1024,
// dynamic smem SK_MAX*8 = 64 KB.
// ---------------------------------------------------------------------------
__global__ void __launch_bounds__(1024) finish_kernel(
        const float* __restrict__ scores,
        const float* __restrict__ anchors,
        const float* __restrict__ breg,
        float* __restrict__ out,
        int A, int k) {
    extern __shared__ unsigned long long skeys[];    // SK_MAX
    __shared__ unsigned int start[SUBB];
    __shared__ unsigned int cursor[SUBB];
    __shared__ unsigned int warp_tot[32];
    __shared__ int sCnt;
    __shared__ int sT;
    __shared__ unsigned int sAb;
    const int b = blockIdx.x;
    const int t = threadIdx.x;
    const size_t base = (size_t)b * (size_t)A;
    unsigned int* gsub = &g_sub[b * SUBB];
    unsigned int T24 = g_T24[b];
    int Ct = g_count[b];
    const int kk = min(k, A);

    if (Ct < kk || Ct > CAND_MAX) {
        // -------- exact fallback, entirely in this block (pathological) -----
        for (int i = t; i < SUBB; i += 1024) { cursor[i] = 0; gsub[i] = 0; }
        if (t == 0) sCnt = 0;
        __syncthreads();
        for (int i = t; i < A; i += 1024)
            atomicAdd(&cursor[mono_f32(scores[base + i]) >> 20], 1u);
        __syncthreads();
        suffix_threshold(cursor, (unsigned)kk, warp_tot, &sT, &sAb);
        __syncthreads();
        T24 = (unsigned)sT << 12;
        __syncthreads();
        for (int i = t; i < A; i += 1024) {
            unsigned int m = mono_f32(scores[base + i]);
            if ((m >> 8) >= T24) {
                unsigned long long key = ((unsigned long long)m << 32) |
                                         (unsigned long long)(0xFFFFFFFFu - (unsigned)i);
                int p = atomicAdd(&sCnt, 1);
                if (p < CAND_MAX) g_cand[(size_t)b * CAND_MAX + p] = key;
                atomicAdd(&gsub[min((m >> 8) - T24, 4095u)], 1u);
            }
        }
        __syncthreads();
        Ct = min(sCnt, CAND_MAX);
    }

    // -------- load digit hist, zero global copy, build start/cursor ---------
    unsigned int h0 = gsub[t * 4], h1 = gsub[t * 4 + 1],
                 h2 = gsub[t * 4 + 2], h3 = gsub[t * 4 + 3];
    gsub[t * 4] = 0; gsub[t * 4 + 1] = 0; gsub[t * 4 + 2] = 0; gsub[t * 4 + 3] = 0;

    const int lane = t & 31, wid = t >> 5;
    unsigned int seg = h0 + h1 + h2 + h3;
    unsigned int suf = seg;
#pragma unroll
    for (int d = 1; d < 32; d <<= 1) {
        unsigned int v = __shfl_down_sync(0xFFFFFFFFu, suf, d);
        if (lane + d < 32) suf += v;
    }
    if (lane == 0) warp_tot[wid] = suf;
    __syncthreads();
    if (wid == 0) {
        unsigned int wv = warp_tot[lane];
        unsigned int wsuf = wv;
#pragma unroll
        for (int d = 1; d < 32; d <<= 1) {
            unsigned int v = __shfl_down_sync(0xFFFFFFFFu, wsuf, d);
            if (lane + d < 32) wsuf += v;
        }
        warp_tot[lane] = wsuf - wv;
    }
    __syncthreads();
    const unsigned int above = (suf - seg) + warp_tot[wid];  // digits > my top bin
    unsigned int st3 = above;
    unsigned int st2 = st3 + h3;
    unsigned int st1 = st2 + h2;
    unsigned int st0 = st1 + h1;
    start[t * 4 + 0] = st0; cursor[t * 4 + 0] = st0;
    start[t * 4 + 1] = st1; cursor[t * 4 + 1] = st1;
    start[t * 4 + 2] = st2; cursor[t * 4 + 2] = st2;
    start[t * 4 + 3] = st3; cursor[t * 4 + 3] = st3;
    __syncthreads();

    // -------- scatter candidates into digit-sorted order --------------------
    const unsigned long long* cand = &g_cand[(size_t)b * CAND_MAX];
    unsigned long long* gt = &g_trim[(size_t)b * CAND_MAX];
    const bool fits = (Ct <= SK_MAX);
    for (int i = t; i < Ct; i += 1024) {
        unsigned long long key = cand[i];
        unsigned int dig = min((unsigned)(key >> 40) - T24, 4095u);
        unsigned int pos = atomicAdd(&cursor[dig], 1u);
        if (fits) skeys[pos] = key; else gt[pos] = key;
    }
    __syncthreads();
    const unsigned long long* keys = fits ? skeys : gt;

    // -------- exact rank via tiny intra-digit scans; decode ------------------
    for (int p = t; p < Ct; p += 1024) {
        unsigned long long key = keys[p];
        unsigned int dig = min((unsigned)(key >> 40) - T24, 4095u);
        int gs = (int)start[dig];
        int ge = (dig > 0) ? (int)start[dig - 1] : Ct;
        int r = gs;
        for (int j = gs; j < ge; j++) r += (keys[j] > key);
        if (r < k) decode_one(key, r, anchors, breg, out, base, b, k);
    }
}

// ---------------------------------------------------------------------------
extern "C" void kernel_launch(void* const* d_in, const int* in_sizes, int n_in,
                              void* d_out, int out_size) {
    const float* anchors    = (const float*)d_in[0];
    const float* objectness = (const float*)d_in[1];
    const float* breg       = (const float*)d_in[2];
    float* out = (float*)d_out;

    const int NA = in_sizes[1];
    const int k  = 2000;
    const int N  = out_size / (k * 5);
    const int A  = NA / N;

    static bool attr_set = false;
    if (!attr_set) {
        cudaFuncSetAttribute(finish_kernel,
                             cudaFuncAttributeMaxDynamicSharedMemorySize,
                             SK_MAX * (int)sizeof(unsigned long long));
        attr_set = true;
    }

    sample_thresh_kernel<<<N, 1024>>>(objectness, A, k);
    compact_kernel<<<dim3(BPB, N), HT>>>(objectness, A);
    finish_kernel<<<N, 1024, SK_MAX * sizeof(unsigned long long)>>>(
        objectness, anchors, breg, out, A, k);
}